// round 8
// baseline (speedup 1.0000x reference)
#include <cuda_runtime.h>
#include <cstdint>

// Problem constants (fixed by the reference):
//   NUM_BLOCKS=8192, BLOCK_SIZE=16, NUM_HEADS=8, HEAD_SIZE=128
//   NUM_TOKENS=65536, NUM_SLOTS = 8192*16 = 131072
//   per-slot payload = 8*128 fp32 = 1024 floats = 4096 bytes = 256 float4
#define NUM_SLOTS       131072
#define NUM_TOKENS      65536
#define VEC4_PER_SLOT   256
#define SLOTS_PER_BLOCK 4

// Inverse slot map, encoded token+1 (0 = slot untouched).
// INVARIANT: all-zero at entry to kernel_launch. Zero-initialized at module
// load; the merge kernel restores every entry it consumes back to zero, so
// every call sees the same initial state and does identical work.
__device__ int g_inv_map[NUM_SLOTS];

// 4 tokens per thread via one int4 load; 4 scattered 4B stores each.
__global__ void __launch_bounds__(512) scatter_inv_map_kernel(
    const int4* __restrict__ slot_mapping)
{
    int i = blockIdx.x * blockDim.x + threadIdx.x;   // i in [0, NUM_TOKENS/4)
    const int4 s = slot_mapping[i];
    const int base = 4 * i + 1;                      // token+1 encoding
    g_inv_map[s.x] = base + 0;
    g_inv_map[s.y] = base + 1;
    g_inv_map[s.z] = base + 2;
    g_inv_map[s.w] = base + 3;
}

// One block per 4 consecutive slots; 256 threads each move float4 #t of each
// of the 4 slots. 4 independent 16B loads front-batched per thread (MLP=4),
// fully coalesced, occ ~84%. Streaming hints: zero reuse. PDL: the grid is
// launched overlapping the scatter kernel; cudaGridDependencySynchronize()
// gates the first dependent read (the map). After reading its 4 map entries
// (single int4), the block restores them to zero behind a barrier.
__global__ void __launch_bounds__(256, 8) merge_write_kernel(
    const float4* __restrict__ to_cache,
    const float4* __restrict__ kv_cache,
    float4* __restrict__ out)
{
    const unsigned slot_base = blockIdx.x * SLOTS_PER_BLOCK;
    const unsigned t = threadIdx.x;

    // Wait for the scatter grid's writes to be visible.
    cudaGridDependencySynchronize();

    // All 4 map entries in one 16B broadcast load.
    const int4 m = *(const int4*)&g_inv_map[slot_base];
    const int srcs[SLOTS_PER_BLOCK] = { m.x, m.y, m.z, m.w };

    const float4* srcp[SLOTS_PER_BLOCK];
#pragma unroll
    for (int s = 0; s < SLOTS_PER_BLOCK; s++) {
        const unsigned slot = slot_base + s;
        srcp[s] = (srcs[s] > 0) ? (to_cache + (size_t)(srcs[s] - 1) * VEC4_PER_SLOT)
                                : (kv_cache + (size_t)slot * VEC4_PER_SLOT);
    }

    // Front-batch the 4 independent payload loads (in flight across the barrier).
    float4 v[SLOTS_PER_BLOCK];
#pragma unroll
    for (int s = 0; s < SLOTS_PER_BLOCK; s++)
        v[s] = __ldcs(srcp[s] + t);

    // All warps have read the map entries; now it is safe to clear them.
    __syncthreads();
    if (t == 0)
        *(int4*)&g_inv_map[slot_base] = make_int4(0, 0, 0, 0);

#pragma unroll
    for (int s = 0; s < SLOTS_PER_BLOCK; s++)
        __stcs(out + (size_t)(slot_base + s) * VEC4_PER_SLOT + t, v[s]);
}

extern "C" void kernel_launch(void* const* d_in, const int* in_sizes, int n_in,
                              void* d_out, int out_size)
{
    const float4* to_cache     = (const float4*)d_in[0];  // [65536, 8, 128] f32
    const float4* kv_cache     = (const float4*)d_in[1];  // [8192, 16, 8, 128] f32
    const int4*   slot_mapping = (const int4*)d_in[2];    // [65536] i32, as int4
    float4*       out          = (float4*)d_out;          // full updated kv_cache

    scatter_inv_map_kernel<<<NUM_TOKENS / 4 / 512, 512>>>(slot_mapping);

    // Launch merge with Programmatic Stream Serialization: its front-end
    // overlaps the scatter kernel; correctness is gated by the in-kernel
    // cudaGridDependencySynchronize().
    cudaLaunchConfig_t cfg = {};
    cfg.gridDim  = dim3(NUM_SLOTS / SLOTS_PER_BLOCK, 1, 1);
    cfg.blockDim = dim3(256, 1, 1);
    cudaLaunchAttribute attrs[1];
    attrs[0].id = cudaLaunchAttributeProgrammaticStreamSerialization;
    attrs[0].val.programmaticStreamSerializationAllowed = 1;
    cfg.attrs = attrs;
    cfg.numAttrs = 1;
    cudaLaunchKernelEx(&cfg, merge_write_kernel, to_cache, kv_cache, out);
}